// round 16
// baseline (speedup 1.0000x reference)
#include <cuda_runtime.h>

// Problem dims (fixed by reference setup_inputs)
#define B_DIM 8192
#define T_DIM 2048
#define H     20
#define CTA_ROWS 64       // batch rows per CTA
#define NTHR  256         // 8 warps; warps 0-3 own 3 units, warps 4-7 own 2
#define PSRC  10          // source units pinned in registers (120 regs heavy)

typedef unsigned long long u64;

// Scratch (allocation-free rule: __device__ globals)
// g_xT padded by one t-row so the prefetch needs no bounds branch.
__device__ float g_xT[(size_t)(T_DIM + 1) * B_DIM];   // x transposed: [t][b]
__device__ float g_outT[(size_t)T_DIM * B_DIM];       // out transposed: [t][b]

// ---------------- f32x2 helpers ----------------
__device__ __forceinline__ u64 pk(float lo, float hi) {
    u64 r; asm("mov.b64 %0,{%1,%2};" : "=l"(r) : "f"(lo), "f"(hi)); return r;
}
__device__ __forceinline__ void upk(u64 v, float& lo, float& hi) {
    asm("mov.b64 {%0,%1},%2;" : "=f"(lo), "=f"(hi) : "l"(v));
}
__device__ __forceinline__ u64 fma2(u64 a, u64 b, u64 c) {
    u64 d; asm("fma.rn.f32x2 %0,%1,%2,%3;" : "=l"(d) : "l"(a), "l"(b), "l"(c)); return d;
}
__device__ __forceinline__ float tanh_a(float x) {
    float r; asm("tanh.approx.f32 %0,%1;" : "=f"(r) : "f"(x)); return r;
}

// LSTM cell via MUFU.TANH: 5 MUFU + ~9 FMA-pipe ops.
__device__ __forceinline__ void cell(float ig, float fg, float gg, float og,
                                     float& c, float& h) {
    float si = fmaf(0.5f, tanh_a(0.5f * ig), 0.5f);
    float sf = fmaf(0.5f, tanh_a(0.5f * fg), 0.5f);
    float so = fmaf(0.5f, tanh_a(0.5f * og), 0.5f);
    float tg = tanh_a(gg);
    float cn = sf * c + si * tg;
    float tc = tanh_a(cn);
    c = cn;
    h = so * tc;
}

// ---------------- transposes ----------------
__global__ void transpose_in(const float* __restrict__ in) {
    __shared__ float tile[32][33];
    int c0 = blockIdx.x * 32, r0 = blockIdx.y * 32;
    int tx = threadIdx.x, ty = threadIdx.y;
#pragma unroll
    for (int i = 0; i < 32; i += 8)
        tile[ty + i][tx] = in[(size_t)(r0 + ty + i) * T_DIM + c0 + tx];
    __syncthreads();
#pragma unroll
    for (int i = 0; i < 32; i += 8)
        g_xT[(size_t)(c0 + ty + i) * B_DIM + r0 + tx] = tile[tx][ty + i];
}

__global__ void transpose_out(float* __restrict__ out) {
    __shared__ float tile[32][33];
    int c0 = blockIdx.x * 32, r0 = blockIdx.y * 32;
    int tx = threadIdx.x, ty = threadIdx.y;
#pragma unroll
    for (int i = 0; i < 32; i += 8)
        tile[ty + i][tx] = g_outT[(size_t)(r0 + ty + i) * B_DIM + c0 + tx];
    __syncthreads();
#pragma unroll
    for (int i = 0; i < 32; i += 8)
        out[(size_t)(c0 + ty + i) * T_DIM + r0 + tx] = tile[tx][ty + i];
}

// Slot -> (gate-row ka, gate-row kb) mapping.
// Warps 0-3: units ub=3w,3w+1,3w+2. Slots 0-3: gate s of pair (ub,ub+1).
//            Slot 4: (i,f) of ub+2. Slot 5: (g,o) of ub+2.
// Warps 4-7: units ub=12+2(w-4). Slots 0-3 only.
__device__ __forceinline__ bool slot_rows(int w, int s, int& ka, int& kb) {
    if (w < 4) {
        int ub = 3 * w;
        if (s < 4)      { ka = s * H + ub;     kb = ka + 1; }
        else if (s == 4){ ka = 0 * H + ub + 2; kb = 1 * H + ub + 2; }
        else            { ka = 2 * H + ub + 2; kb = 3 * H + ub + 2; }
        return true;
    } else {
        int ub = 12 + 2 * (w - 4);
        if (s < 4) { ka = s * H + ub; kb = ka + 1; return true; }
        return false;
    }
}

// ---------------- main persistent LSTM kernel ----------------
// Round-15 structure (best) + round-16 micro: PSRC=10, branch-free x
// prefetch (padded g_xT), time loop unrolled by 2 (compile-time buffers).
__global__ __launch_bounds__(NTHR, 1) void lstm_kernel(
    const float* __restrict__ W1, const float* __restrict__ b1,
    const float* __restrict__ W_ih, const float* __restrict__ W_hh,
    const float* __restrict__ b_ih, const float* __restrict__ b_hh,
    const float* __restrict__ W2, const float* __restrict__ b2)
{
    __shared__ __align__(16) u64 WQ[H][8][6];     // [src][warp][slot]  7.7 KB
    __shared__ __align__(16) u64 uvu[8][6], uvv[8][6];
    __shared__ u64 w2p[H];                        // (W2[u], W2[u]) duplicated
    __shared__ float b2_s;
    __shared__ __align__(8) float h_s[2][H][CTA_ROWS];  // 10.2 KB

    const int tid  = threadIdx.x;
    const int lane = tid & 31;
    const int wid  = tid >> 5;
    const int rowbase = blockIdx.x * CTA_ROWS;
    const int rA = 2 * lane;

    // --- one-time setup ---
    for (int i = tid; i < H * 48; i += NTHR) {
        int src = i / 48, r = i % 48, w = r / 6, s = r % 6;
        int ka, kb;
        WQ[src][w][s] = slot_rows(w, s, ka, kb)
            ? pk(W_hh[ka * H + src], W_hh[kb * H + src]) : 0ULL;
    }
    if (tid < 48) {
        int w = tid / 6, s = tid % 6, ka, kb;
        if (slot_rows(w, s, ka, kb)) {
            float sua = 0.f, sva = 0.f, sub = 0.f, svb = 0.f;
            for (int u = 0; u < H; ++u) {
                sua += W_ih[ka * H + u] * W1[u];
                sva += W_ih[ka * H + u] * b1[u];
                sub += W_ih[kb * H + u] * W1[u];
                svb += W_ih[kb * H + u] * b1[u];
            }
            uvu[w][s] = pk(sua, sub);
            uvv[w][s] = pk(sva + b_ih[ka] + b_hh[ka], svb + b_ih[kb] + b_hh[kb]);
        } else { uvu[w][s] = 0ULL; uvv[w][s] = 0ULL; }
    }
    if (tid < H) { float wv = W2[tid]; w2p[tid] = pk(wv, wv); }
    if (tid == 0) b2_s = b2[0];
    for (int i = tid; i < 2 * H * CTA_ROWS; i += NTHR) h_s[0][0][i] = 0.f;
    __syncthreads();

    const int ub = (wid < 4) ? 3 * wid : 12 + 2 * (wid - 4);

    u64 uu[6], vv[6];
#pragma unroll
    for (int s = 0; s < 6; ++s) { uu[s] = uvu[wid][s]; vv[s] = uvv[wid][s]; }

    // pinned weights for sources [0, PSRC)
    u64 wp[PSRC][6];
#pragma unroll
    for (int u = 0; u < PSRC; ++u)
#pragma unroll
        for (int s = 0; s < 6; ++s) wp[u][s] = WQ[u][wid][s];

    u64 c2[3] = {0ULL, 0ULL, 0ULL};

    float2 xv = *(const float2*)(g_xT + rowbase + rA);

#pragma unroll 1
    for (int t0 = 0; t0 < T_DIM; t0 += 2) {
#pragma unroll
        for (int half = 0; half < 2; ++half) {
            const int t   = t0 + half;           // compile-time parity
            const int cur = half, nxt = half ^ 1;

            // branch-free prefetch (g_xT padded by one t-row)
            float2 xnext = *(const float2*)(
                g_xT + (size_t)(t + 1) * B_DIM + rowbase + rA);

            // ---- preload full h vector (u64 = (h[rowA], h[rowB])) ----
            u64 h2[H];
#pragma unroll
            for (int u = 0; u < H; ++u)
                h2[u] = *(const u64*)&h_s[cur][u][rA];

            // ---- out[t-1]: rotates across light warps 4-7 ----
            if (t > 0 && wid == 4 + (t & 3)) {
                u64 oacc = pk(b2_s, b2_s);
#pragma unroll
                for (int u = 0; u < H; ++u)
                    oacc = fma2(w2p[u], h2[u], oacc);
                float o0, o1; upk(oacc, o0, o1);
                *(float2*)(g_outT + (size_t)(t - 1) * B_DIM + rowbase + rA) =
                    make_float2(o0, o1);
            }

            u64 xA2 = pk(xv.x, xv.x), xB2 = pk(xv.y, xv.y);

            if (wid < 4) {
                // ===== heavy path, FMA/MUFU interleaved =====
                u64 aA[4], aB[4];
#pragma unroll
                for (int s = 0; s < 4; ++s) {
                    aA[s] = fma2(xA2, uu[s], vv[s]);
                    aB[s] = fma2(xB2, uu[s], vv[s]);
                }
#pragma unroll
                for (int u = 0; u < PSRC; ++u) {
                    float hA, hB; upk(h2[u], hA, hB);
                    u64 hpA = pk(hA, hA), hpB = pk(hB, hB);
#pragma unroll
                    for (int s = 0; s < 4; ++s) {
                        aA[s] = fma2(wp[u][s], hpA, aA[s]);
                        aB[s] = fma2(wp[u][s], hpB, aB[s]);
                    }
                }
#pragma unroll
                for (int u = PSRC; u < H; ++u) {
                    float hA, hB; upk(h2[u], hA, hB);
                    u64 hpA = pk(hA, hA), hpB = pk(hB, hB);
                    ulonglong2 q0 = *(const ulonglong2*)&WQ[u][wid][0];
                    ulonglong2 q1 = *(const ulonglong2*)&WQ[u][wid][2];
                    aA[0] = fma2(q0.x, hpA, aA[0]);  aB[0] = fma2(q0.x, hpB, aB[0]);
                    aA[1] = fma2(q0.y, hpA, aA[1]);  aB[1] = fma2(q0.y, hpB, aB[1]);
                    aA[2] = fma2(q1.x, hpA, aA[2]);  aB[2] = fma2(q1.x, hpB, aB[2]);
                    aA[3] = fma2(q1.y, hpA, aA[3]);  aB[3] = fma2(q1.y, hpB, aB[3]);
                }

                // pair cells (MUFU) — independent of solo-slot FMAs below
                float iA0,iA1,fA0,fA1,gA0,gA1,oA0,oA1;
                float iB0,iB1,fB0,fB1,gB0,gB1,oB0,oB1;
                upk(aA[0],iA0,iA1); upk(aA[1],fA0,fA1);
                upk(aA[2],gA0,gA1); upk(aA[3],oA0,oA1);
                upk(aB[0],iB0,iB1); upk(aB[1],fB0,fB1);
                upk(aB[2],gB0,gB1); upk(aB[3],oB0,oB1);

                float cA, cB, hA, hB;
                upk(c2[0], cA, cB);
                cell(iA0, fA0, gA0, oA0, cA, hA);
                cell(iB0, fB0, gB0, oB0, cB, hB);
                c2[0] = pk(cA, cB);
                *(u64*)&h_s[nxt][ub][rA] = pk(hA, hB);

                upk(c2[1], cA, cB);
                cell(iA1, fA1, gA1, oA1, cA, hA);
                cell(iB1, fB1, gB1, oB1, cB, hB);
                c2[1] = pk(cA, cB);
                *(u64*)&h_s[nxt][ub + 1][rA] = pk(hA, hB);

                // solo slots 4-5 (unit ub+2): independent FFMA2 under tanh
                u64 sA0 = fma2(xA2, uu[4], vv[4]), sB0 = fma2(xB2, uu[4], vv[4]);
                u64 sA1 = fma2(xA2, uu[5], vv[5]), sB1 = fma2(xB2, uu[5], vv[5]);
#pragma unroll
                for (int u = 0; u < PSRC; ++u) {
                    float h0, h1; upk(h2[u], h0, h1);
                    u64 hpA = pk(h0, h0), hpB = pk(h1, h1);
                    sA0 = fma2(wp[u][4], hpA, sA0);  sB0 = fma2(wp[u][4], hpB, sB0);
                    sA1 = fma2(wp[u][5], hpA, sA1);  sB1 = fma2(wp[u][5], hpB, sB1);
                }
#pragma unroll
                for (int u = PSRC; u < H; ++u) {
                    float h0, h1; upk(h2[u], h0, h1);
                    u64 hpA = pk(h0, h0), hpB = pk(h1, h1);
                    ulonglong2 q2 = *(const ulonglong2*)&WQ[u][wid][4];
                    sA0 = fma2(q2.x, hpA, sA0);  sB0 = fma2(q2.x, hpB, sB0);
                    sA1 = fma2(q2.y, hpA, sA1);  sB1 = fma2(q2.y, hpB, sB1);
                }
                float ifA0, ifA1, goA0, goA1, ifB0, ifB1, goB0, goB1;
                upk(sA0, ifA0, ifA1); upk(sA1, goA0, goA1);
                upk(sB0, ifB0, ifB1); upk(sB1, goB0, goB1);

                upk(c2[2], cA, cB);
                cell(ifA0, ifA1, goA0, goA1, cA, hA);
                cell(ifB0, ifB1, goB0, goB1, cB, hB);
                c2[2] = pk(cA, cB);
                *(u64*)&h_s[nxt][ub + 2][rA] = pk(hA, hB);
            } else {
                // ===== light path: 2 units, 4 slots =====
                u64 aA[4], aB[4];
#pragma unroll
                for (int s = 0; s < 4; ++s) {
                    aA[s] = fma2(xA2, uu[s], vv[s]);
                    aB[s] = fma2(xB2, uu[s], vv[s]);
                }
#pragma unroll
                for (int u = 0; u < PSRC; ++u) {
                    float hA, hB; upk(h2[u], hA, hB);
                    u64 hpA = pk(hA, hA), hpB = pk(hB, hB);
#pragma unroll
                    for (int s = 0; s < 4; ++s) {
                        aA[s] = fma2(wp[u][s], hpA, aA[s]);
                        aB[s] = fma2(wp[u][s], hpB, aB[s]);
                    }
                }
#pragma unroll
                for (int u = PSRC; u < H; ++u) {
                    float hA, hB; upk(h2[u], hA, hB);
                    u64 hpA = pk(hA, hA), hpB = pk(hB, hB);
                    ulonglong2 q0 = *(const ulonglong2*)&WQ[u][wid][0];
                    ulonglong2 q1 = *(const ulonglong2*)&WQ[u][wid][2];
                    aA[0] = fma2(q0.x, hpA, aA[0]);  aB[0] = fma2(q0.x, hpB, aB[0]);
                    aA[1] = fma2(q0.y, hpA, aA[1]);  aB[1] = fma2(q0.y, hpB, aB[1]);
                    aA[2] = fma2(q1.x, hpA, aA[2]);  aB[2] = fma2(q1.x, hpB, aB[2]);
                    aA[3] = fma2(q1.y, hpA, aA[3]);  aB[3] = fma2(q1.y, hpB, aB[3]);
                }
                float iA0,iA1,fA0,fA1,gA0,gA1,oA0,oA1;
                float iB0,iB1,fB0,fB1,gB0,gB1,oB0,oB1;
                upk(aA[0],iA0,iA1); upk(aA[1],fA0,fA1);
                upk(aA[2],gA0,gA1); upk(aA[3],oA0,oA1);
                upk(aB[0],iB0,iB1); upk(aB[1],fB0,fB1);
                upk(aB[2],gB0,gB1); upk(aB[3],oB0,oB1);

                float cA, cB, hA, hB;
                upk(c2[0], cA, cB);
                cell(iA0, fA0, gA0, oA0, cA, hA);
                cell(iB0, fB0, gB0, oB0, cB, hB);
                c2[0] = pk(cA, cB);
                *(u64*)&h_s[nxt][ub][rA] = pk(hA, hB);

                upk(c2[1], cA, cB);
                cell(iA1, fA1, gA1, oA1, cA, hA);
                cell(iB1, fB1, gB1, oB1, cB, hB);
                c2[1] = pk(cA, cB);
                *(u64*)&h_s[nxt][ub + 1][rA] = pk(hA, hB);
            }

            // single barrier per step
            __syncthreads();

            xv = xnext;
        }
    }

    // final out[T-1] from buffer (T_DIM & 1) == buffer 0 after even T
    if (wid == 4) {
        const int cur = T_DIM & 1;
        u64 oacc = pk(b2_s, b2_s);
#pragma unroll
        for (int u = 0; u < H; ++u)
            oacc = fma2(w2p[u], *(const u64*)&h_s[cur][u][rA], oacc);
        float o0, o1; upk(oacc, o0, o1);
        *(float2*)(g_outT + (size_t)(T_DIM - 1) * B_DIM + rowbase + rA) =
            make_float2(o0, o1);
    }
}

// ---------------- launcher ----------------
extern "C" void kernel_launch(void* const* d_in, const int* in_sizes, int n_in,
                              void* d_out, int out_size)
{
    const float* x    = (const float*)d_in[0];
    const float* W1   = (const float*)d_in[1];
    const float* b1   = (const float*)d_in[2];
    const float* W_ih = (const float*)d_in[3];
    const float* W_hh = (const float*)d_in[4];
    const float* b_ih = (const float*)d_in[5];
    const float* b_hh = (const float*)d_in[6];
    const float* W2   = (const float*)d_in[7];
    const float* b2   = (const float*)d_in[8];
    float* out = (float*)d_out;

    (void)in_sizes; (void)n_in; (void)out_size;

    // x[B][T] -> g_xT[T][B]
    transpose_in<<<dim3(T_DIM / 32, B_DIM / 32), dim3(32, 8)>>>(x);

    // recurrent scan
    lstm_kernel<<<B_DIM / CTA_ROWS, NTHR>>>(W1, b1, W_ih, W_hh, b_ih, b_hh, W2, b2);

    // g_outT[T][B] -> out[B][T]
    transpose_out<<<dim3(B_DIM / 32, T_DIM / 32), dim3(32, 8)>>>(out);
}

// round 17
// speedup vs baseline: 1.1150x; 1.1150x over previous
#include <cuda_runtime.h>

// Problem dims (fixed by reference setup_inputs)
#define B_DIM 8192
#define T_DIM 2048
#define H     20
#define CTA_ROWS 64       // batch rows per CTA
#define NTHR  256         // 8 warps; warps 0-3 own 3 units, warps 4-7 own 2
#define PSRC  8           // source units pinned in registers (round-15 value)

typedef unsigned long long u64;

// Scratch (allocation-free rule: __device__ globals)
// g_xT padded by one t-row so the prefetch needs no bounds branch.
__device__ float g_xT[(size_t)(T_DIM + 1) * B_DIM];   // x transposed: [t][b]
__device__ float g_outT[(size_t)T_DIM * B_DIM];       // out transposed: [t][b]

// ---------------- f32x2 helpers ----------------
__device__ __forceinline__ u64 pk(float lo, float hi) {
    u64 r; asm("mov.b64 %0,{%1,%2};" : "=l"(r) : "f"(lo), "f"(hi)); return r;
}
__device__ __forceinline__ void upk(u64 v, float& lo, float& hi) {
    asm("mov.b64 {%0,%1},%2;" : "=f"(lo), "=f"(hi) : "l"(v));
}
__device__ __forceinline__ u64 fma2(u64 a, u64 b, u64 c) {
    u64 d; asm("fma.rn.f32x2 %0,%1,%2,%3;" : "=l"(d) : "l"(a), "l"(b), "l"(c)); return d;
}
__device__ __forceinline__ float tanh_a(float x) {
    float r; asm("tanh.approx.f32 %0,%1;" : "=f"(r) : "f"(x)); return r;
}

// LSTM cell via MUFU.TANH: 5 MUFU + ~9 FMA-pipe ops.
__device__ __forceinline__ void cell(float ig, float fg, float gg, float og,
                                     float& c, float& h) {
    float si = fmaf(0.5f, tanh_a(0.5f * ig), 0.5f);
    float sf = fmaf(0.5f, tanh_a(0.5f * fg), 0.5f);
    float so = fmaf(0.5f, tanh_a(0.5f * og), 0.5f);
    float tg = tanh_a(gg);
    float cn = sf * c + si * tg;
    float tc = tanh_a(cn);
    c = cn;
    h = so * tc;
}

// ---------------- transposes ----------------
__global__ void transpose_in(const float* __restrict__ in) {
    __shared__ float tile[32][33];
    int c0 = blockIdx.x * 32, r0 = blockIdx.y * 32;
    int tx = threadIdx.x, ty = threadIdx.y;
#pragma unroll
    for (int i = 0; i < 32; i += 8)
        tile[ty + i][tx] = in[(size_t)(r0 + ty + i) * T_DIM + c0 + tx];
    __syncthreads();
#pragma unroll
    for (int i = 0; i < 32; i += 8)
        g_xT[(size_t)(c0 + ty + i) * B_DIM + r0 + tx] = tile[tx][ty + i];
}

__global__ void transpose_out(float* __restrict__ out) {
    __shared__ float tile[32][33];
    int c0 = blockIdx.x * 32, r0 = blockIdx.y * 32;
    int tx = threadIdx.x, ty = threadIdx.y;
#pragma unroll
    for (int i = 0; i < 32; i += 8)
        tile[ty + i][tx] = g_outT[(size_t)(r0 + ty + i) * B_DIM + c0 + tx];
    __syncthreads();
#pragma unroll
    for (int i = 0; i < 32; i += 8)
        out[(size_t)(c0 + ty + i) * T_DIM + r0 + tx] = tile[tx][ty + i];
}

// Slot -> (gate-row ka, gate-row kb) mapping.
// Warps 0-3: units ub=3w,3w+1,3w+2. Slots 0-3: gate s of pair (ub,ub+1).
//            Slot 4: (i,f) of ub+2. Slot 5: (g,o) of ub+2.
// Warps 4-7: units ub=12+2(w-4). Slots 0-3 only.
__device__ __forceinline__ bool slot_rows(int w, int s, int& ka, int& kb) {
    if (w < 4) {
        int ub = 3 * w;
        if (s < 4)      { ka = s * H + ub;     kb = ka + 1; }
        else if (s == 4){ ka = 0 * H + ub + 2; kb = 1 * H + ub + 2; }
        else            { ka = 2 * H + ub + 2; kb = 3 * H + ub + 2; }
        return true;
    } else {
        int ub = 12 + 2 * (w - 4);
        if (s < 4) { ka = s * H + ub; kb = ka + 1; return true; }
        return false;
    }
}

// ---------------- main persistent LSTM kernel ----------------
// EXACT round-15 structure (best: 1851.6 us) with ONE isolated change:
// branch-free x prefetch via the padded g_xT (no PSRC change, no unroll —
// those were the round-16 regression).
__global__ __launch_bounds__(NTHR, 1) void lstm_kernel(
    const float* __restrict__ W1, const float* __restrict__ b1,
    const float* __restrict__ W_ih, const float* __restrict__ W_hh,
    const float* __restrict__ b_ih, const float* __restrict__ b_hh,
    const float* __restrict__ W2, const float* __restrict__ b2)
{
    __shared__ __align__(16) u64 WQ[H][8][6];     // [src][warp][slot]  7.7 KB
    __shared__ __align__(16) u64 uvu[8][6], uvv[8][6];
    __shared__ u64 w2p[H];                        // (W2[u], W2[u]) duplicated
    __shared__ float b2_s;
    __shared__ __align__(8) float h_s[2][H][CTA_ROWS];  // 10.2 KB

    const int tid  = threadIdx.x;
    const int lane = tid & 31;
    const int wid  = tid >> 5;
    const int rowbase = blockIdx.x * CTA_ROWS;
    const int rA = 2 * lane;

    // --- one-time setup ---
    for (int i = tid; i < H * 48; i += NTHR) {
        int src = i / 48, r = i % 48, w = r / 6, s = r % 6;
        int ka, kb;
        WQ[src][w][s] = slot_rows(w, s, ka, kb)
            ? pk(W_hh[ka * H + src], W_hh[kb * H + src]) : 0ULL;
    }
    if (tid < 48) {
        int w = tid / 6, s = tid % 6, ka, kb;
        if (slot_rows(w, s, ka, kb)) {
            float sua = 0.f, sva = 0.f, sub = 0.f, svb = 0.f;
            for (int u = 0; u < H; ++u) {
                sua += W_ih[ka * H + u] * W1[u];
                sva += W_ih[ka * H + u] * b1[u];
                sub += W_ih[kb * H + u] * W1[u];
                svb += W_ih[kb * H + u] * b1[u];
            }
            uvu[w][s] = pk(sua, sub);
            uvv[w][s] = pk(sva + b_ih[ka] + b_hh[ka], svb + b_ih[kb] + b_hh[kb]);
        } else { uvu[w][s] = 0ULL; uvv[w][s] = 0ULL; }
    }
    if (tid < H) { float wv = W2[tid]; w2p[tid] = pk(wv, wv); }
    if (tid == 0) b2_s = b2[0];
    for (int i = tid; i < 2 * H * CTA_ROWS; i += NTHR) h_s[0][0][i] = 0.f;
    __syncthreads();

    const int ub = (wid < 4) ? 3 * wid : 12 + 2 * (wid - 4);

    u64 uu[6], vv[6];
#pragma unroll
    for (int s = 0; s < 6; ++s) { uu[s] = uvu[wid][s]; vv[s] = uvv[wid][s]; }

    // pinned weights for sources [0, PSRC): 48 u64 = 96 regs (heavy path)
    u64 wp[PSRC][6];
#pragma unroll
    for (int u = 0; u < PSRC; ++u)
#pragma unroll
        for (int s = 0; s < 6; ++s) wp[u][s] = WQ[u][wid][s];

    u64 c2[3] = {0ULL, 0ULL, 0ULL};   // cell state per owned unit: (rowA, rowB)

    float2 xv = *(const float2*)(g_xT + rowbase + rA);

    for (int t = 0; t < T_DIM; ++t) {
        const int cur = t & 1, nxt = cur ^ 1;

        // branch-free prefetch (g_xT padded by one t-row)
        float2 xnext = *(const float2*)(
            g_xT + (size_t)(t + 1) * B_DIM + rowbase + rA);

        // ---- preload full h vector (u64 = (h[rowA], h[rowB])) ----
        u64 h2[H];
#pragma unroll
        for (int u = 0; u < H; ++u)
            h2[u] = *(const u64*)&h_s[cur][u][rA];

        // ---- out[t-1]: rotates across light warps 4-7 ----
        if (t > 0 && wid == 4 + (t & 3)) {
            u64 oacc = pk(b2_s, b2_s);
#pragma unroll
            for (int u = 0; u < H; ++u)
                oacc = fma2(w2p[u], h2[u], oacc);    // (outA, outB)
            float o0, o1; upk(oacc, o0, o1);
            *(float2*)(g_outT + (size_t)(t - 1) * B_DIM + rowbase + rA) =
                make_float2(o0, o1);
        }

        u64 xA2 = pk(xv.x, xv.x), xB2 = pk(xv.y, xv.y);

        if (wid < 4) {
            // ===== heavy path, FMA/MUFU interleaved =====
            u64 aA[4], aB[4];
#pragma unroll
            for (int s = 0; s < 4; ++s) {
                aA[s] = fma2(xA2, uu[s], vv[s]);
                aB[s] = fma2(xB2, uu[s], vv[s]);
            }
#pragma unroll
            for (int u = 0; u < PSRC; ++u) {
                float hA, hB; upk(h2[u], hA, hB);
                u64 hpA = pk(hA, hA), hpB = pk(hB, hB);
#pragma unroll
                for (int s = 0; s < 4; ++s) {
                    aA[s] = fma2(wp[u][s], hpA, aA[s]);
                    aB[s] = fma2(wp[u][s], hpB, aB[s]);
                }
            }
#pragma unroll
            for (int u = PSRC; u < H; ++u) {
                float hA, hB; upk(h2[u], hA, hB);
                u64 hpA = pk(hA, hA), hpB = pk(hB, hB);
                ulonglong2 q0 = *(const ulonglong2*)&WQ[u][wid][0];
                ulonglong2 q1 = *(const ulonglong2*)&WQ[u][wid][2];
                aA[0] = fma2(q0.x, hpA, aA[0]);  aB[0] = fma2(q0.x, hpB, aB[0]);
                aA[1] = fma2(q0.y, hpA, aA[1]);  aB[1] = fma2(q0.y, hpB, aB[1]);
                aA[2] = fma2(q1.x, hpA, aA[2]);  aB[2] = fma2(q1.x, hpB, aB[2]);
                aA[3] = fma2(q1.y, hpA, aA[3]);  aB[3] = fma2(q1.y, hpB, aB[3]);
            }

            // pair cells (MUFU chains) — independent of solo-slot FMAs below
            float iA0,iA1,fA0,fA1,gA0,gA1,oA0,oA1;
            float iB0,iB1,fB0,fB1,gB0,gB1,oB0,oB1;
            upk(aA[0],iA0,iA1); upk(aA[1],fA0,fA1);
            upk(aA[2],gA0,gA1); upk(aA[3],oA0,oA1);
            upk(aB[0],iB0,iB1); upk(aB[1],fB0,fB1);
            upk(aB[2],gB0,gB1); upk(aB[3],oB0,oB1);

            float cA, cB, hA, hB;
            upk(c2[0], cA, cB);
            cell(iA0, fA0, gA0, oA0, cA, hA);
            cell(iB0, fB0, gB0, oB0, cB, hB);
            c2[0] = pk(cA, cB);
            *(u64*)&h_s[nxt][ub][rA] = pk(hA, hB);

            upk(c2[1], cA, cB);
            cell(iA1, fA1, gA1, oA1, cA, hA);
            cell(iB1, fB1, gB1, oB1, cB, hB);
            c2[1] = pk(cA, cB);
            *(u64*)&h_s[nxt][ub + 1][rA] = pk(hA, hB);

            // solo slots 4-5 (unit ub+2): independent FFMA2 under tanh chains
            u64 sA0 = fma2(xA2, uu[4], vv[4]), sB0 = fma2(xB2, uu[4], vv[4]);
            u64 sA1 = fma2(xA2, uu[5], vv[5]), sB1 = fma2(xB2, uu[5], vv[5]);
#pragma unroll
            for (int u = 0; u < PSRC; ++u) {
                float h0, h1; upk(h2[u], h0, h1);
                u64 hpA = pk(h0, h0), hpB = pk(h1, h1);
                sA0 = fma2(wp[u][4], hpA, sA0);  sB0 = fma2(wp[u][4], hpB, sB0);
                sA1 = fma2(wp[u][5], hpA, sA1);  sB1 = fma2(wp[u][5], hpB, sB1);
            }
#pragma unroll
            for (int u = PSRC; u < H; ++u) {
                float h0, h1; upk(h2[u], h0, h1);
                u64 hpA = pk(h0, h0), hpB = pk(h1, h1);
                ulonglong2 q2 = *(const ulonglong2*)&WQ[u][wid][4];
                sA0 = fma2(q2.x, hpA, sA0);  sB0 = fma2(q2.x, hpB, sB0);
                sA1 = fma2(q2.y, hpA, sA1);  sB1 = fma2(q2.y, hpB, sB1);
            }
            float ifA0, ifA1, goA0, goA1, ifB0, ifB1, goB0, goB1;
            upk(sA0, ifA0, ifA1); upk(sA1, goA0, goA1);
            upk(sB0, ifB0, ifB1); upk(sB1, goB0, goB1);

            upk(c2[2], cA, cB);
            cell(ifA0, ifA1, goA0, goA1, cA, hA);
            cell(ifB0, ifB1, goB0, goB1, cB, hB);
            c2[2] = pk(cA, cB);
            *(u64*)&h_s[nxt][ub + 2][rA] = pk(hA, hB);
        } else {
            // ===== light path: 2 units, 4 slots =====
            u64 aA[4], aB[4];
#pragma unroll
            for (int s = 0; s < 4; ++s) {
                aA[s] = fma2(xA2, uu[s], vv[s]);
                aB[s] = fma2(xB2, uu[s], vv[s]);
            }
#pragma unroll
            for (int u = 0; u < PSRC; ++u) {
                float hA, hB; upk(h2[u], hA, hB);
                u64 hpA = pk(hA, hA), hpB = pk(hB, hB);
#pragma unroll
                for (int s = 0; s < 4; ++s) {
                    aA[s] = fma2(wp[u][s], hpA, aA[s]);
                    aB[s] = fma2(wp[u][s], hpB, aB[s]);
                }
            }
#pragma unroll
            for (int u = PSRC; u < H; ++u) {
                float hA, hB; upk(h2[u], hA, hB);
                u64 hpA = pk(hA, hA), hpB = pk(hB, hB);
                ulonglong2 q0 = *(const ulonglong2*)&WQ[u][wid][0];
                ulonglong2 q1 = *(const ulonglong2*)&WQ[u][wid][2];
                aA[0] = fma2(q0.x, hpA, aA[0]);  aB[0] = fma2(q0.x, hpB, aB[0]);
                aA[1] = fma2(q0.y, hpA, aA[1]);  aB[1] = fma2(q0.y, hpB, aB[1]);
                aA[2] = fma2(q1.x, hpA, aA[2]);  aB[2] = fma2(q1.x, hpB, aB[2]);
                aA[3] = fma2(q1.y, hpA, aA[3]);  aB[3] = fma2(q1.y, hpB, aB[3]);
            }
            float iA0,iA1,fA0,fA1,gA0,gA1,oA0,oA1;
            float iB0,iB1,fB0,fB1,gB0,gB1,oB0,oB1;
            upk(aA[0],iA0,iA1); upk(aA[1],fA0,fA1);
            upk(aA[2],gA0,gA1); upk(aA[3],oA0,oA1);
            upk(aB[0],iB0,iB1); upk(aB[1],fB0,fB1);
            upk(aB[2],gB0,gB1); upk(aB[3],oB0,oB1);

            float cA, cB, hA, hB;
            upk(c2[0], cA, cB);
            cell(iA0, fA0, gA0, oA0, cA, hA);
            cell(iB0, fB0, gB0, oB0, cB, hB);
            c2[0] = pk(cA, cB);
            *(u64*)&h_s[nxt][ub][rA] = pk(hA, hB);

            upk(c2[1], cA, cB);
            cell(iA1, fA1, gA1, oA1, cA, hA);
            cell(iB1, fB1, gB1, oB1, cB, hB);
            c2[1] = pk(cA, cB);
            *(u64*)&h_s[nxt][ub + 1][rA] = pk(hA, hB);
        }

        // single barrier per step (top-level: all 256 threads arrive)
        __syncthreads();

        xv = xnext;
    }

    // final out[T-1] from buffer (T_DIM & 1)
    if (wid == 4) {
        const int cur = T_DIM & 1;
        u64 oacc = pk(b2_s, b2_s);
#pragma unroll
        for (int u = 0; u < H; ++u)
            oacc = fma2(w2p[u], *(const u64*)&h_s[cur][u][rA], oacc);
        float o0, o1; upk(oacc, o0, o1);
        *(float2*)(g_outT + (size_t)(T_DIM - 1) * B_DIM + rowbase + rA) =
            make_float2(o0, o1);
    }
}

// ---------------- launcher ----------------
extern "C" void kernel_launch(void* const* d_in, const int* in_sizes, int n_in,
                              void* d_out, int out_size)
{
    const float* x    = (const float*)d_in[0];
    const float* W1   = (const float*)d_in[1];
    const float* b1   = (const float*)d_in[2];
    const float* W_ih = (const float*)d_in[3];
    const float* W_hh = (const float*)d_in[4];
    const float* b_ih = (const float*)d_in[5];
    const float* b_hh = (const float*)d_in[6];
    const float* W2   = (const float*)d_in[7];
    const float* b2   = (const float*)d_in[8];
    float* out = (float*)d_out;

    (void)in_sizes; (void)n_in; (void)out_size;

    // x[B][T] -> g_xT[T][B]
    transpose_in<<<dim3(T_DIM / 32, B_DIM / 32), dim3(32, 8)>>>(x);

    // recurrent scan: round-15 structure + branch-free prefetch only
    lstm_kernel<<<B_DIM / CTA_ROWS, NTHR>>>(W1, b1, W_ih, W_hh, b_ih, b_hh, W2, b2);

    // g_outT[T][B] -> out[B][T]
    transpose_out<<<dim3(B_DIM / 32, T_DIM / 32), dim3(32, 8)>>>(out);
}